// round 2
// baseline (speedup 1.0000x reference)
#include <cuda_runtime.h>

#define NB    1024
#define DIN   784
#define NH1   2048
#define NH2   10
#define NK    10
#define NU    2832      // DIN + NH1
#define NL    128
#define TSTEPS 20
#define NTOT  (NB * DIN)   // 802816

// ---------------- device state (no allocations allowed) ----------------
__device__ float g_x[NB * DIN];
__device__ float g_h1m[NB * NH1];
__device__ float g_h1s[NB * NH1];
__device__ float g_h2m[NB * NH2];
__device__ float g_h2s[NB * NH2];
__device__ float g_h2sum[NB * NH2];
__device__ float g_xs[DIN];
__device__ float g_hs[NH1];
__device__ float g_v1[NU];
__device__ float g_v2[NU];
__device__ float g_scal[3];   // a1, a2, cs

// ---------------- threefry2x32 (20 rounds), bit-exact vs JAX ----------------
__device__ __forceinline__ void threefry(unsigned k0, unsigned k1,
                                         unsigned x0, unsigned x1,
                                         unsigned& o0, unsigned& o1) {
    unsigned k2 = k0 ^ k1 ^ 0x1BD11BDAu;
    x0 += k0; x1 += k1;
#define RO(r) x0 += x1; x1 = __funnelshift_l(x1, x1, (r)); x1 ^= x0;
    RO(13) RO(15) RO(26) RO(6)   x0 += k1; x1 += k2 + 1u;
    RO(17) RO(29) RO(16) RO(24)  x0 += k2; x1 += k0 + 2u;
    RO(13) RO(15) RO(26) RO(6)   x0 += k0; x1 += k1 + 3u;
    RO(17) RO(29) RO(16) RO(24)  x0 += k1; x1 += k2 + 4u;
    RO(13) RO(15) RO(26) RO(6)   x0 += k2; x1 += k0 + 5u;
#undef RO
    o0 = x0; o1 = x1;
}

// ---------------- init: zero all persistent state ----------------
__global__ void k_init() {
    int stride = gridDim.x * blockDim.x;
    for (int idx = blockIdx.x * blockDim.x + threadIdx.x; idx < NB * NH1; idx += stride) {
        g_h1m[idx] = 0.f; g_h1s[idx] = 0.f;
        if (idx < NB * NH2) { g_h2m[idx] = 0.f; g_h2s[idx] = 0.f; g_h2sum[idx] = 0.f; }
        if (idx < DIN) g_xs[idx] = 0.f;
        if (idx < NH1) g_hs[idx] = 0.f;
        if (idx < 3)   g_scal[idx] = 0.f;
    }
}

// ---------------- precompute val1/val2 over core memory ----------------
__global__ void k_val(const float* __restrict__ vec, const int* __restrict__ cnt) {
    int u = blockIdx.x * blockDim.x + threadIdx.x;
    if (u >= NU) return;
    float v1 = 0.f, v2 = 0.f;
    for (int k = 0; k < NK; k++) {
        const float* p = vec + ((size_t)k * NU + u) * NL;
        int last = -1;
        for (int l = 0; l < NL; l += 4) {
            float4 q = *(const float4*)(p + l);
            if (q.x != 0.f) last = l;
            if (q.y != 0.f) last = l + 1;
            if (q.z != 0.f) last = l + 2;
            if (q.w != 0.f) last = l + 3;
        }
        int c = cnt[k * NU + u];
        if (c > 0) {
            v2 += (float)c;
            if (last >= 0) v1 += (float)(last - 1);   // last_idx - 1 (can be -1)
        }
    }
    g_v1[u] = v1; g_v2[u] = v2;
}

// ---------------- per-step spikes: JAX partitionable threefry ----------------
// For element i: bits = o0 ^ o1 where (o0,o1) = threefry(folded_key, (0, i)).
// Thread <-> column c; each thread covers 16 batch rows -> one xs atomic per thread.
__global__ __launch_bounds__(256) void k_rng(const float* __restrict__ inp, int t) {
    int c = blockIdx.x * blockDim.x + threadIdx.x;
    if (c >= DIN) return;
    unsigned fk0, fk1;
    threefry(0u, 42u, 0u, (unsigned)t, fk0, fk1);   // fold_in(key(42), t)
    int r0 = blockIdx.y * 16;
    float sum = 0.f;
#pragma unroll 4
    for (int r = 0; r < 16; r++) {
        int i = (r0 + r) * DIN + c;
        unsigned o0, o1;
        threefry(fk0, fk1, 0u, (unsigned)i, o0, o1);
        unsigned b = o0 ^ o1;
        float u = __uint_as_float((b >> 9) | 0x3f800000u) - 1.0f;
        float x = inp[i] > u ? 1.0f : 0.0f;
        g_x[i] = x;
        sum += x;
    }
    atomicAdd(&g_xs[c], sum);
}

// ---------------- GEMM1 fused: h1m = h1m*0.2*(1-h1s) + x@W1^T + b1 ; h1s=(h1m>0.5) ; hs += colsum(h1s)
// C tile: 64(M) x 128(N), 256 threads, 8x4 micro, K-tile 16
__global__ __launch_bounds__(256) void k_gemm1(const float* __restrict__ W1,
                                               const float* __restrict__ b1) {
    __shared__ float As[16][68];     // [k][m], padded
    __shared__ float Bs[16][132];    // [k][n], padded
    __shared__ float shs[128];

    int tid = threadIdx.x;
    int nb = blockIdx.x * 128;
    int mb = blockIdx.y * 64;
    int tr = tid >> 5, tcx = tid & 31;
    int m0 = tr * 8, n0 = tcx * 4;

    float acc[8][4];
#pragma unroll
    for (int i = 0; i < 8; i++)
#pragma unroll
        for (int q = 0; q < 4; q++) acc[i][q] = 0.f;

    int arow = tid >> 2, ak = (tid & 3) * 4;
    const float* Aptr = g_x + (size_t)(mb + arow) * DIN + ak;
    int i0 = tid, i1 = tid + 256;
    int br0 = i0 >> 2, bk0 = (i0 & 3) * 4;
    int br1 = i1 >> 2, bk1 = (i1 & 3) * 4;
    const float* Bp0 = W1 + (size_t)(nb + br0) * DIN + bk0;
    const float* Bp1 = W1 + (size_t)(nb + br1) * DIN + bk1;

    for (int kt = 0; kt < DIN; kt += 16) {
        float4 av  = *(const float4*)(Aptr + kt);
        float4 bv0 = *(const float4*)(Bp0 + kt);
        float4 bv1 = *(const float4*)(Bp1 + kt);
        __syncthreads();
        As[ak + 0][arow] = av.x; As[ak + 1][arow] = av.y;
        As[ak + 2][arow] = av.z; As[ak + 3][arow] = av.w;
        Bs[bk0 + 0][br0] = bv0.x; Bs[bk0 + 1][br0] = bv0.y;
        Bs[bk0 + 2][br0] = bv0.z; Bs[bk0 + 3][br0] = bv0.w;
        Bs[bk1 + 0][br1] = bv1.x; Bs[bk1 + 1][br1] = bv1.y;
        Bs[bk1 + 2][br1] = bv1.z; Bs[bk1 + 3][br1] = bv1.w;
        __syncthreads();
#pragma unroll
        for (int k = 0; k < 16; k++) {
            float4 a0 = *(const float4*)&As[k][m0];
            float4 a1 = *(const float4*)&As[k][m0 + 4];
            float4 bq = *(const float4*)&Bs[k][n0];
            float am[8] = {a0.x, a0.y, a0.z, a0.w, a1.x, a1.y, a1.z, a1.w};
#pragma unroll
            for (int i = 0; i < 8; i++) {
                acc[i][0] += am[i] * bq.x;
                acc[i][1] += am[i] * bq.y;
                acc[i][2] += am[i] * bq.z;
                acc[i][3] += am[i] * bq.w;
            }
        }
    }

    if (tid < 128) shs[tid] = 0.f;
    __syncthreads();

    float4 bias = *(const float4*)(b1 + nb + n0);
    float ssum0 = 0.f, ssum1 = 0.f, ssum2 = 0.f, ssum3 = 0.f;
#pragma unroll
    for (int i = 0; i < 8; i++) {
        size_t idx = (size_t)(mb + m0 + i) * NH1 + nb + n0;
        float4 om = *(const float4*)(g_h1m + idx);
        float4 os = *(const float4*)(g_h1s + idx);
        float4 c, s;
        c.x = acc[i][0] + bias.x + om.x * 0.2f * (1.f - os.x);
        c.y = acc[i][1] + bias.y + om.y * 0.2f * (1.f - os.y);
        c.z = acc[i][2] + bias.z + om.z * 0.2f * (1.f - os.z);
        c.w = acc[i][3] + bias.w + om.w * 0.2f * (1.f - os.w);
        s.x = c.x > 0.5f ? 1.f : 0.f;
        s.y = c.y > 0.5f ? 1.f : 0.f;
        s.z = c.z > 0.5f ? 1.f : 0.f;
        s.w = c.w > 0.5f ? 1.f : 0.f;
        *(float4*)(g_h1m + idx) = c;
        *(float4*)(g_h1s + idx) = s;
        ssum0 += s.x; ssum1 += s.y; ssum2 += s.z; ssum3 += s.w;
    }
    atomicAdd(&shs[n0 + 0], ssum0);
    atomicAdd(&shs[n0 + 1], ssum1);
    atomicAdd(&shs[n0 + 2], ssum2);
    atomicAdd(&shs[n0 + 3], ssum3);
    __syncthreads();
    if (tid < 128) atomicAdd(&g_hs[nb + tid], shs[tid]);
}

// ---------------- layer-2 LIF update (4 batch rows per block) ----------------
__global__ __launch_bounds__(256) void k_h2(const float* __restrict__ W2,
                                            const float* __restrict__ b2) {
    int b0 = blockIdx.x * 4;
    int tid = threadIdx.x;
    float acc[4][10];
#pragma unroll
    for (int r = 0; r < 4; r++)
#pragma unroll
        for (int k = 0; k < 10; k++) acc[r][k] = 0.f;

    for (int j = tid; j < NH1; j += 256) {
        float w[10];
#pragma unroll
        for (int k = 0; k < 10; k++) w[k] = W2[k * NH1 + j];
#pragma unroll
        for (int r = 0; r < 4; r++) {
            float s = g_h1s[(size_t)(b0 + r) * NH1 + j];
#pragma unroll
            for (int k = 0; k < 10; k++) acc[r][k] += s * w[k];
        }
    }
#pragma unroll
    for (int r = 0; r < 4; r++)
#pragma unroll
        for (int k = 0; k < 10; k++)
#pragma unroll
            for (int o = 16; o; o >>= 1)
                acc[r][k] += __shfl_down_sync(0xffffffffu, acc[r][k], o);

    __shared__ float sh[8][40];
    int lane = tid & 31, wrp = tid >> 5;
    if (lane == 0) {
#pragma unroll
        for (int r = 0; r < 4; r++)
#pragma unroll
            for (int k = 0; k < 10; k++) sh[wrp][r * 10 + k] = acc[r][k];
    }
    __syncthreads();
    if (tid < 40) {
        float v = 0.f;
#pragma unroll
        for (int w8 = 0; w8 < 8; w8++) v += sh[w8][tid];
        int r = tid / 10, k = tid % 10;
        int idx = (b0 + r) * NH2 + k;
        float m = g_h2m[idx] * 0.2f * (1.f - g_h2s[idx]) + v + b2[k];
        float s = m > 0.5f ? 1.f : 0.f;
        g_h2m[idx] = m; g_h2s[idx] = s; g_h2sum[idx] += s;
    }
}

// ---------------- per-step scalar dots + zero xs/hs for next step ----------------
__global__ void k_dot() {
    int tid = threadIdx.x;
    float t1 = 0.f, t2 = 0.f, tc = 0.f;
    for (int u = tid; u < NU; u += 256) {
        float w = (u < DIN) ? g_xs[u] : g_hs[u - DIN];
        t1 += w * g_v1[u];
        t2 += w * g_v2[u];
        tc += w;
    }
    __shared__ float s1[256], s2[256], sc[256];
    s1[tid] = t1; s2[tid] = t2; sc[tid] = tc;
    __syncthreads();
    for (int o = 128; o; o >>= 1) {
        if (tid < o) { s1[tid] += s1[tid + o]; s2[tid] += s2[tid + o]; sc[tid] += sc[tid + o]; }
        __syncthreads();
    }
    if (tid == 0) { g_scal[0] += s1[0]; g_scal[1] += s2[0]; g_scal[2] += sc[0]; }
    __syncthreads();
    for (int u = tid; u < DIN; u += 256) g_xs[u] = 0.f;
    for (int u = tid; u < NH1; u += 256) g_hs[u] = 0.f;
}

// ---------------- output: (h2sum/T, a1, a2, cs) ----------------
__global__ void k_out(float* __restrict__ out) {
    int i = blockIdx.x * blockDim.x + threadIdx.x;
    if (i < NB * NH2) out[i] = g_h2sum[i] / (float)TSTEPS;
    else if (i < NB * NH2 + 3) out[i] = g_scal[i - NB * NH2];
}

extern "C" void kernel_launch(void* const* d_in, const int* in_sizes, int n_in,
                              void* d_out, int out_size) {
    const float* inp = (const float*)d_in[0];
    const float* W1  = (const float*)d_in[1];
    const float* b1  = (const float*)d_in[2];
    const float* W2  = (const float*)d_in[3];
    const float* b2  = (const float*)d_in[4];
    const float* cmv = (const float*)d_in[5];
    const int*   cmc = (const int*)d_in[6];
    // time_window fixed at 20 (graph structure must be static)

    k_init<<<2048, 256>>>();
    k_val<<<(NU + 255) / 256, 256>>>(cmv, cmc);

    for (int t = 0; t < TSTEPS; t++) {
        dim3 gr((DIN + 255) / 256, NB / 16);
        k_rng<<<gr, 256>>>(inp, t);
        dim3 g1(NH1 / 128, NB / 64);
        k_gemm1<<<g1, 256>>>(W1, b1);
        k_h2<<<NB / 4, 256>>>(W2, b2);
        k_dot<<<1, 256>>>();
    }
    k_out<<<(NB * NH2 + 3 + 255) / 256, 256>>>((float*)d_out);
}

// round 5
// speedup vs baseline: 1.1484x; 1.1484x over previous
#include <cuda_runtime.h>
#include <cuda_bf16.h>
#include <cstdint>

typedef unsigned int u32;

#define NB    1024
#define DIN   784
#define NH1   2048
#define NH2   10
#define NK    10
#define NU    2832      // DIN + NH1
#define NL    128
#define TSTEPS 20
#define KSTEPS_PER_PLANE 49     // 784/16
#define KK_TOTAL 147            // 3 planes * 49

// ---------------- device state (no allocations allowed) ----------------
__device__ __nv_bfloat16 g_xb[NB * DIN];          // spikes as bf16 (0/1)
__device__ __nv_bfloat16 g_wsp[3 * NH1 * DIN];    // W1 split into 3 bf16 planes
__device__ float g_h1m[NB * NH1];
__device__ float g_h1s[NB * NH1];
__device__ float g_h2m[NB * NH2];
__device__ float g_h2s[NB * NH2];
__device__ float g_h2sum[NB * NH2];
__device__ float g_xs[DIN];
__device__ float g_hs[NH1];
__device__ float g_v1[NU];
__device__ float g_v2[NU];
__device__ float g_scal[3];   // a1, a2, cs

// ---------------- threefry2x32 (20 rounds), bit-exact vs JAX ----------------
__device__ __forceinline__ void threefry(unsigned k0, unsigned k1,
                                         unsigned x0, unsigned x1,
                                         unsigned& o0, unsigned& o1) {
    unsigned k2 = k0 ^ k1 ^ 0x1BD11BDAu;
    x0 += k0; x1 += k1;
#define RO(r) x0 += x1; x1 = __funnelshift_l(x1, x1, (r)); x1 ^= x0;
    RO(13) RO(15) RO(26) RO(6)   x0 += k1; x1 += k2 + 1u;
    RO(17) RO(29) RO(16) RO(24)  x0 += k2; x1 += k0 + 2u;
    RO(13) RO(15) RO(26) RO(6)   x0 += k0; x1 += k1 + 3u;
    RO(17) RO(29) RO(16) RO(24)  x0 += k1; x1 += k2 + 4u;
    RO(13) RO(15) RO(26) RO(6)   x0 += k2; x1 += k0 + 5u;
#undef RO
    o0 = x0; o1 = x1;
}

// ---------------- PTX wrappers (inline functions, scalar refs) ----------------
__device__ __forceinline__ void ldm4(u32 addr, u32& r0, u32& r1, u32& r2, u32& r3) {
    asm volatile("ldmatrix.sync.aligned.m8n8.x4.shared.b16 {%0,%1,%2,%3}, [%4];"
                 : "=r"(r0), "=r"(r1), "=r"(r2), "=r"(r3) : "r"(addr));
}

__device__ __forceinline__ void mma16816(float& c0, float& c1, float& c2, float& c3,
                                         u32 a0, u32 a1, u32 a2, u32 a3,
                                         u32 b0, u32 b1) {
    asm volatile("mma.sync.aligned.m16n8k16.row.col.f32.bf16.bf16.f32 "
                 "{%0,%1,%2,%3},{%4,%5,%6,%7},{%8,%9},{%0,%1,%2,%3};"
                 : "+f"(c0), "+f"(c1), "+f"(c2), "+f"(c3)
                 : "r"(a0), "r"(a1), "r"(a2), "r"(a3), "r"(b0), "r"(b1));
}

// ---------------- init: zero all persistent state ----------------
__global__ void k_init() {
    int stride = gridDim.x * blockDim.x;
    for (int idx = blockIdx.x * blockDim.x + threadIdx.x; idx < NB * NH1; idx += stride) {
        g_h1m[idx] = 0.f; g_h1s[idx] = 0.f;
        if (idx < NB * NH2) { g_h2m[idx] = 0.f; g_h2s[idx] = 0.f; g_h2sum[idx] = 0.f; }
        if (idx < DIN) g_xs[idx] = 0.f;
        if (idx < NH1) g_hs[idx] = 0.f;
        if (idx < 3)   g_scal[idx] = 0.f;
    }
}

// ---------------- lossless 3-way bf16 split of W1 ----------------
__global__ void k_split(const float* __restrict__ W1) {
    int i = blockIdx.x * blockDim.x + threadIdx.x;
    if (i >= NH1 * DIN) return;
    float w = W1[i];
    __nv_bfloat16 hb = __float2bfloat16_rn(w);
    float hi = __bfloat162float(hb);
    __nv_bfloat16 mb = __float2bfloat16_rn(w - hi);
    float mid = __bfloat162float(mb);
    __nv_bfloat16 lb = __float2bfloat16_rn(w - hi - mid);
    g_wsp[i] = hb;
    g_wsp[NH1 * DIN + i] = mb;
    g_wsp[2 * NH1 * DIN + i] = lb;
}

// ---------------- precompute val1/val2 over core memory ----------------
__global__ void k_val(const float* __restrict__ vec, const int* __restrict__ cnt) {
    int u = blockIdx.x * blockDim.x + threadIdx.x;
    if (u >= NU) return;
    float v1 = 0.f, v2 = 0.f;
    for (int k = 0; k < NK; k++) {
        const float* p = vec + ((size_t)k * NU + u) * NL;
        int last = -1;
        for (int l = 0; l < NL; l += 4) {
            float4 q = *(const float4*)(p + l);
            if (q.x != 0.f) last = l;
            if (q.y != 0.f) last = l + 1;
            if (q.z != 0.f) last = l + 2;
            if (q.w != 0.f) last = l + 3;
        }
        int c = cnt[k * NU + u];
        if (c > 0) {
            v2 += (float)c;
            if (last >= 0) v1 += (float)(last - 1);
        }
    }
    g_v1[u] = v1; g_v2[u] = v2;
}

// ---------------- per-step spikes: JAX partitionable threefry ----------------
__global__ __launch_bounds__(256) void k_rng(const float* __restrict__ inp, int t) {
    int c = blockIdx.x * blockDim.x + threadIdx.x;
    if (c >= DIN) return;
    unsigned fk0, fk1;
    threefry(0u, 42u, 0u, (unsigned)t, fk0, fk1);   // fold_in(key(42), t)
    int r0 = blockIdx.y * 16;
    float sum = 0.f;
#pragma unroll 4
    for (int r = 0; r < 16; r++) {
        int i = (r0 + r) * DIN + c;
        unsigned o0, o1;
        threefry(fk0, fk1, 0u, (unsigned)i, o0, o1);
        unsigned b = o0 ^ o1;
        float u = __uint_as_float((b >> 9) | 0x3f800000u) - 1.0f;
        float x = inp[i] > u ? 1.0f : 0.0f;
        g_xb[i] = __float2bfloat16_rn(x);
        sum += x;
    }
    atomicAdd(&g_xs[c], sum);
}

// ---------------- tensor-core GEMM1 + fused LIF epilogue ----------------
// C tile 64(M) x 128(N), 8 warps (2x4), warp tile 32x32, mma m16n8k16 bf16,
// K' = 3 planes x 784, double-buffered smem (48B row stride, conflict-free).
__global__ __launch_bounds__(256) void k_gemm1t(const float* __restrict__ b1) {
    __shared__ __align__(16) unsigned char smA[2][64 * 48];
    __shared__ __align__(16) unsigned char smB[2][128 * 48];
    __shared__ float shs[128];

    int tid = threadIdx.x;
    int warp = tid >> 5, lane = tid & 31;
    int nb = blockIdx.x * 128, mb = blockIdx.y * 64;
    int wm = (warp >> 2) * 32, wn = (warp & 3) * 32;
    if (tid < 128) shs[tid] = 0.f;

    float acc[2][4][4];
#pragma unroll
    for (int i = 0; i < 2; i++)
#pragma unroll
        for (int j = 0; j < 4; j++)
#pragma unroll
            for (int q = 0; q < 4; q++) acc[i][j][q] = 0.f;

    // gmem->smem loader assignment: 4 bf16 (8B) per slot
    int lrow = tid >> 2, lkg = tid & 3;

    u32 saA = (u32)__cvta_generic_to_shared(smA);
    u32 saB = (u32)__cvta_generic_to_shared(smB);

    // prologue: tile kk=0 (plane 0, k0=0)
    uint2 ra  = *(const uint2*)&g_xb[(mb + lrow) * DIN + lkg * 4];
    uint2 rb0 = *(const uint2*)&g_wsp[(nb + lrow) * DIN + lkg * 4];
    uint2 rb1 = *(const uint2*)&g_wsp[(nb + lrow + 64) * DIN + lkg * 4];
    *(uint2*)&smA[0][lrow * 48 + lkg * 8] = ra;
    *(uint2*)&smB[0][lrow * 48 + lkg * 8] = rb0;
    *(uint2*)&smB[0][(lrow + 64) * 48 + lkg * 8] = rb1;
    __syncthreads();

    // ldmatrix byte offsets (within one buffer)
    u32 aoff0 = (u32)((wm + (lane & 15)) * 48 + (lane >> 4) * 16);
    u32 aoff1 = aoff0 + 16 * 48;
    u32 boff  = (u32)((wn + (lane & 7) + ((lane >> 4) & 1) * 8) * 48 +
                      ((lane >> 3) & 1) * 16);

    for (int kk = 0; kk < KK_TOTAL; kk++) {
        int cur = kk & 1;
        if (kk < KK_TOTAL - 1) {
            int kn = kk + 1;
            int p = kn / KSTEPS_PER_PLANE;
            int k0 = (kn - p * KSTEPS_PER_PLANE) * 16;
            const __nv_bfloat16* wp = g_wsp + (size_t)p * NH1 * DIN;
            ra  = *(const uint2*)&g_xb[(mb + lrow) * DIN + k0 + lkg * 4];
            rb0 = *(const uint2*)&wp[(nb + lrow) * DIN + k0 + lkg * 4];
            rb1 = *(const uint2*)&wp[(nb + lrow + 64) * DIN + k0 + lkg * 4];
        }

        u32 a0, a1, a2, a3, a4, a5, a6, a7;
        u32 p0, p1, p2, p3, q0, q1, q2, q3;
        u32 baseA = saA + (u32)cur * (64 * 48);
        u32 baseB = saB + (u32)cur * (128 * 48);
        ldm4(baseA + aoff0, a0, a1, a2, a3);
        ldm4(baseA + aoff1, a4, a5, a6, a7);
        ldm4(baseB + boff,           p0, p1, p2, p3);   // n-cols wn..wn+15
        ldm4(baseB + boff + 16 * 48, q0, q1, q2, q3);   // n-cols wn+16..wn+31

        mma16816(acc[0][0][0], acc[0][0][1], acc[0][0][2], acc[0][0][3], a0, a1, a2, a3, p0, p1);
        mma16816(acc[0][1][0], acc[0][1][1], acc[0][1][2], acc[0][1][3], a0, a1, a2, a3, p2, p3);
        mma16816(acc[0][2][0], acc[0][2][1], acc[0][2][2], acc[0][2][3], a0, a1, a2, a3, q0, q1);
        mma16816(acc[0][3][0], acc[0][3][1], acc[0][3][2], acc[0][3][3], a0, a1, a2, a3, q2, q3);
        mma16816(acc[1][0][0], acc[1][0][1], acc[1][0][2], acc[1][0][3], a4, a5, a6, a7, p0, p1);
        mma16816(acc[1][1][0], acc[1][1][1], acc[1][1][2], acc[1][1][3], a4, a5, a6, a7, p2, p3);
        mma16816(acc[1][2][0], acc[1][2][1], acc[1][2][2], acc[1][2][3], a4, a5, a6, a7, q0, q1);
        mma16816(acc[1][3][0], acc[1][3][1], acc[1][3][2], acc[1][3][3], a4, a5, a6, a7, q2, q3);

        if (kk < KK_TOTAL - 1) {
            int nxt = cur ^ 1;
            *(uint2*)&smA[nxt][lrow * 48 + lkg * 8] = ra;
            *(uint2*)&smB[nxt][lrow * 48 + lkg * 8] = rb0;
            *(uint2*)&smB[nxt][(lrow + 64) * 48 + lkg * 8] = rb1;
        }
        __syncthreads();
    }

    // ---------------- fused LIF epilogue ----------------
    // C fragment: c0,c1 -> (row = lane>>2, cols cp,cp+1); c2,c3 -> row+8
    int r0 = lane >> 2, cp = (lane & 3) * 2;
    float csum[4][2];
#pragma unroll
    for (int j = 0; j < 4; j++) { csum[j][0] = 0.f; csum[j][1] = 0.f; }

#pragma unroll
    for (int j = 0; j < 4; j++) {
        int col = nb + wn + j * 8 + cp;
        float2 bias = *(const float2*)&b1[col];
#pragma unroll
        for (int i = 0; i < 2; i++) {
#pragma unroll
            for (int h = 0; h < 2; h++) {
                int row = mb + wm + i * 16 + r0 + h * 8;
                size_t idx = (size_t)row * NH1 + col;
                float2 om = *(float2*)&g_h1m[idx];
                float2 os = *(float2*)&g_h1s[idx];
                float v0 = acc[i][j][2 * h + 0] + bias.x + om.x * 0.2f * (1.f - os.x);
                float v1 = acc[i][j][2 * h + 1] + bias.y + om.y * 0.2f * (1.f - os.y);
                float s0 = v0 > 0.5f ? 1.f : 0.f;
                float s1 = v1 > 0.5f ? 1.f : 0.f;
                float2 vm = {v0, v1}, vs = {s0, s1};
                *(float2*)&g_h1m[idx] = vm;
                *(float2*)&g_h1s[idx] = vs;
                csum[j][0] += s0; csum[j][1] += s1;
            }
        }
    }
#pragma unroll
    for (int j = 0; j < 4; j++) {
        atomicAdd(&shs[wn + j * 8 + cp],     csum[j][0]);
        atomicAdd(&shs[wn + j * 8 + cp + 1], csum[j][1]);
    }
    __syncthreads();
    if (tid < 128) atomicAdd(&g_hs[nb + tid], shs[tid]);
}

// ---------------- layer-2 LIF update (4 batch rows per block) ----------------
__global__ __launch_bounds__(256) void k_h2(const float* __restrict__ W2,
                                            const float* __restrict__ b2) {
    int b0 = blockIdx.x * 4;
    int tid = threadIdx.x;
    float acc[4][10];
#pragma unroll
    for (int r = 0; r < 4; r++)
#pragma unroll
        for (int k = 0; k < 10; k++) acc[r][k] = 0.f;

    for (int j = tid; j < NH1; j += 256) {
        float w[10];
#pragma unroll
        for (int k = 0; k < 10; k++) w[k] = W2[k * NH1 + j];
#pragma unroll
        for (int r = 0; r < 4; r++) {
            float s = g_h1s[(size_t)(b0 + r) * NH1 + j];
#pragma unroll
            for (int k = 0; k < 10; k++) acc[r][k] += s * w[k];
        }
    }
#pragma unroll
    for (int r = 0; r < 4; r++)
#pragma unroll
        for (int k = 0; k < 10; k++)
#pragma unroll
            for (int o = 16; o; o >>= 1)
                acc[r][k] += __shfl_down_sync(0xffffffffu, acc[r][k], o);

    __shared__ float sh[8][40];
    int lane = tid & 31, wrp = tid >> 5;
    if (lane == 0) {
#pragma unroll
        for (int r = 0; r < 4; r++)
#pragma unroll
            for (int k = 0; k < 10; k++) sh[wrp][r * 10 + k] = acc[r][k];
    }
    __syncthreads();
    if (tid < 40) {
        float v = 0.f;
#pragma unroll
        for (int w8 = 0; w8 < 8; w8++) v += sh[w8][tid];
        int r = tid / 10, k = tid % 10;
        int idx = (b0 + r) * NH2 + k;
        float m = g_h2m[idx] * 0.2f * (1.f - g_h2s[idx]) + v + b2[k];
        float s = m > 0.5f ? 1.f : 0.f;
        g_h2m[idx] = m; g_h2s[idx] = s; g_h2sum[idx] += s;
    }
}

// ---------------- per-step scalar dots + zero xs/hs for next step ----------------
__global__ void k_dot() {
    int tid = threadIdx.x;
    float t1 = 0.f, t2 = 0.f, tc = 0.f;
    for (int u = tid; u < NU; u += 256) {
        float w = (u < DIN) ? g_xs[u] : g_hs[u - DIN];
        t1 += w * g_v1[u];
        t2 += w * g_v2[u];
        tc += w;
    }
    __shared__ float s1[256], s2[256], sc[256];
    s1[tid] = t1; s2[tid] = t2; sc[tid] = tc;
    __syncthreads();
    for (int o = 128; o; o >>= 1) {
        if (tid < o) { s1[tid] += s1[tid + o]; s2[tid] += s2[tid + o]; sc[tid] += sc[tid + o]; }
        __syncthreads();
    }
    if (tid == 0) { g_scal[0] += s1[0]; g_scal[1] += s2[0]; g_scal[2] += sc[0]; }
    __syncthreads();
    for (int u = tid; u < DIN; u += 256) g_xs[u] = 0.f;
    for (int u = tid; u < NH1; u += 256) g_hs[u] = 0.f;
}

// ---------------- output: (h2sum/T, a1, a2, cs) ----------------
__global__ void k_out(float* __restrict__ out) {
    int i = blockIdx.x * blockDim.x + threadIdx.x;
    if (i < NB * NH2) out[i] = g_h2sum[i] / (float)TSTEPS;
    else if (i < NB * NH2 + 3) out[i] = g_scal[i - NB * NH2];
}

extern "C" void kernel_launch(void* const* d_in, const int* in_sizes, int n_in,
                              void* d_out, int out_size) {
    const float* inp = (const float*)d_in[0];
    const float* W1  = (const float*)d_in[1];
    const float* b1  = (const float*)d_in[2];
    const float* W2  = (const float*)d_in[3];
    const float* b2  = (const float*)d_in[4];
    const float* cmv = (const float*)d_in[5];
    const int*   cmc = (const int*)d_in[6];

    k_init<<<2048, 256>>>();
    k_split<<<(NH1 * DIN + 255) / 256, 256>>>(W1);
    k_val<<<(NU + 255) / 256, 256>>>(cmv, cmc);

    for (int t = 0; t < TSTEPS; t++) {
        dim3 gr((DIN + 255) / 256, NB / 16);
        k_rng<<<gr, 256>>>(inp, t);
        dim3 g1(NH1 / 128, NB / 64);
        k_gemm1t<<<g1, 256>>>(b1);
        k_h2<<<NB / 4, 256>>>(W2, b2);
        k_dot<<<1, 256>>>();
    }
    k_out<<<(NB * NH2 + 3 + 255) / 256, 256>>>((float*)d_out);
}

// round 7
// speedup vs baseline: 1.8739x; 1.6317x over previous
#include <cuda_runtime.h>
#include <cuda_bf16.h>
#include <cstdint>

typedef unsigned int u32;
typedef unsigned long long u64;

#define NB    1024
#define DIN   784
#define DINP  832         // padded K per plane: 13 * 64
#define NH1   2048
#define NH2   10
#define NK    10
#define NU    2832        // DIN + NH1
#define NL    128
#define TSTEPS 20
#define NCHUNK 39         // 3 * 832 / 64
#define ABUF  8192        // 64 rows * 128B
#define BBUF  16384       // 128 rows * 128B
#define DSMEM_SZ (3 * (ABUF + BBUF))   // 73728

// ---------------- device state (no allocations allowed) ----------------
__device__ __align__(16) __nv_bfloat16 g_xb[NB * DINP];        // spikes bf16, K-padded
__device__ __align__(16) __nv_bfloat16 g_wsp[3 * NH1 * DINP];  // W1 3-plane bf16 split
__device__ float g_h1m[NB * NH1];
__device__ float g_h1s[NB * NH1];
__device__ float g_h2m[NB * NH2];
__device__ float g_h2s[NB * NH2];
__device__ float g_h2sum[NB * NH2];
__device__ float g_xs[DIN];
__device__ float g_hs[NH1];
__device__ float g_v1[NU];
__device__ float g_v2[NU];
__device__ float g_scal[3];   // a1, a2, cs

// ---------------- threefry2x32 (20 rounds), bit-exact vs JAX ----------------
__device__ __forceinline__ void threefry(unsigned k0, unsigned k1,
                                         unsigned x0, unsigned x1,
                                         unsigned& o0, unsigned& o1) {
    unsigned k2 = k0 ^ k1 ^ 0x1BD11BDAu;
    x0 += k0; x1 += k1;
#define RO(r) x0 += x1; x1 = __funnelshift_l(x1, x1, (r)); x1 ^= x0;
    RO(13) RO(15) RO(26) RO(6)   x0 += k1; x1 += k2 + 1u;
    RO(17) RO(29) RO(16) RO(24)  x0 += k2; x1 += k0 + 2u;
    RO(13) RO(15) RO(26) RO(6)   x0 += k0; x1 += k1 + 3u;
    RO(17) RO(29) RO(16) RO(24)  x0 += k1; x1 += k2 + 4u;
    RO(13) RO(15) RO(26) RO(6)   x0 += k2; x1 += k0 + 5u;
#undef RO
    o0 = x0; o1 = x1;
}

// ---------------- PTX wrappers ----------------
__device__ __forceinline__ void ldm4(u32 addr, u32& r0, u32& r1, u32& r2, u32& r3) {
    asm volatile("ldmatrix.sync.aligned.m8n8.x4.shared.b16 {%0,%1,%2,%3}, [%4];"
                 : "=r"(r0), "=r"(r1), "=r"(r2), "=r"(r3) : "r"(addr));
}
__device__ __forceinline__ void mma16816(float& c0, float& c1, float& c2, float& c3,
                                         u32 a0, u32 a1, u32 a2, u32 a3,
                                         u32 b0, u32 b1) {
    asm volatile("mma.sync.aligned.m16n8k16.row.col.f32.bf16.bf16.f32 "
                 "{%0,%1,%2,%3},{%4,%5,%6,%7},{%8,%9},{%0,%1,%2,%3};"
                 : "+f"(c0), "+f"(c1), "+f"(c2), "+f"(c3)
                 : "r"(a0), "r"(a1), "r"(a2), "r"(a3), "r"(b0), "r"(b1));
}
__device__ __forceinline__ void cpasync16(u32 dst, const void* src) {
    asm volatile("cp.async.cg.shared.global [%0], [%1], 16;" :: "r"(dst), "l"(src) : "memory");
}
__device__ __forceinline__ void cp_commit() {
    asm volatile("cp.async.commit_group;" ::: "memory");
}
__device__ __forceinline__ void cp_wait1() {
    asm volatile("cp.async.wait_group 1;" ::: "memory");
}

// ---------------- init: zero all persistent state ----------------
__global__ void k_init() {
    int stride = gridDim.x * blockDim.x;
    for (int idx = blockIdx.x * blockDim.x + threadIdx.x; idx < NB * NH1; idx += stride) {
        g_h1m[idx] = 0.f; g_h1s[idx] = 0.f;
        if (idx < NB * DINP) g_xb[idx] = __float2bfloat16_rn(0.f);
        if (idx < NB * NH2) { g_h2m[idx] = 0.f; g_h2s[idx] = 0.f; g_h2sum[idx] = 0.f; }
        if (idx < DIN) g_xs[idx] = 0.f;
        if (idx < NH1) g_hs[idx] = 0.f;
        if (idx < 3)   g_scal[idx] = 0.f;
    }
}

// ---------------- lossless 3-way bf16 split of W1 (K-padded) ----------------
__global__ void k_split(const float* __restrict__ W1) {
    int i = blockIdx.x * blockDim.x + threadIdx.x;
    if (i >= NH1 * DINP) return;
    int n = i / DINP, col = i - n * DINP;
    float w = (col < DIN) ? W1[n * DIN + col] : 0.f;
    __nv_bfloat16 hb = __float2bfloat16_rn(w);
    float hi = __bfloat162float(hb);
    __nv_bfloat16 mb = __float2bfloat16_rn(w - hi);
    float mid = __bfloat162float(mb);
    __nv_bfloat16 lb = __float2bfloat16_rn(w - hi - mid);
    g_wsp[i] = hb;
    g_wsp[NH1 * DINP + i] = mb;
    g_wsp[2 * NH1 * DINP + i] = lb;
}

// ---------------- precompute val1/val2 over core memory ----------------
__global__ void k_val(const float* __restrict__ vec, const int* __restrict__ cnt) {
    int u = blockIdx.x * blockDim.x + threadIdx.x;
    if (u >= NU) return;
    float v1 = 0.f, v2 = 0.f;
    for (int k = 0; k < NK; k++) {
        const float* p = vec + ((size_t)k * NU + u) * NL;
        int last = -1;
        for (int l = 0; l < NL; l += 4) {
            float4 q = *(const float4*)(p + l);
            if (q.x != 0.f) last = l;
            if (q.y != 0.f) last = l + 1;
            if (q.z != 0.f) last = l + 2;
            if (q.w != 0.f) last = l + 3;
        }
        int c = cnt[k * NU + u];
        if (c > 0) {
            v2 += (float)c;
            if (last >= 0) v1 += (float)(last - 1);
        }
    }
    g_v1[u] = v1; g_v2[u] = v2;
}

// ---------------- per-step spikes: JAX partitionable threefry ----------------
__global__ __launch_bounds__(256) void k_rng(const float* __restrict__ inp, int t) {
    int c = blockIdx.x * blockDim.x + threadIdx.x;
    if (c >= DIN) return;
    unsigned fk0, fk1;
    threefry(0u, 42u, 0u, (unsigned)t, fk0, fk1);   // fold_in(key(42), t)
    int r0 = blockIdx.y * 16;
    float sum = 0.f;
#pragma unroll 4
    for (int r = 0; r < 16; r++) {
        int i = (r0 + r) * DIN + c;           // logical index for PRNG counter
        unsigned o0, o1;
        threefry(fk0, fk1, 0u, (unsigned)i, o0, o1);
        unsigned b = o0 ^ o1;
        float u = __uint_as_float((b >> 9) | 0x3f800000u) - 1.0f;
        float x = inp[i] > u ? 1.0f : 0.0f;
        g_xb[(r0 + r) * DINP + c] = __float2bfloat16_rn(x);
        sum += x;
    }
    atomicAdd(&g_xs[c], sum);
}

// ---------------- mma.sync GEMM1, 3-stage cp.async pipeline, K-tile 64 ----------------
// C tile 64(M) x 128(N), 8 warps (2x2? no: 2x4), warp tile 32x32.
// smem rows are 128B (64 bf16) with XOR-16B swizzle: addr = row*128 + ((seg ^ (row&7))*16).
__device__ __forceinline__ void load_chunk(int c, u32 aBase, u32 bBase,
                                           int mbc, int nbc, int tid) {
    int kc = c * 64;
    int p = kc / DINP;
    int off = kc - p * DINP;
    const __nv_bfloat16* wpl = g_wsp + (size_t)p * NH1 * DINP;
#pragma unroll
    for (int i = 0; i < 2; i++) {
        int ch = i * 256 + tid;
        int row = ch >> 3, seg = ch & 7;
        u32 sw = (u32)(row * 128 + ((seg ^ (row & 7)) << 4));
        cpasync16(aBase + sw, &g_xb[(size_t)(mbc + row) * DINP + off + seg * 8]);
    }
#pragma unroll
    for (int i = 0; i < 4; i++) {
        int ch = i * 256 + tid;
        int row = ch >> 3, seg = ch & 7;
        u32 sw = (u32)(row * 128 + ((seg ^ (row & 7)) << 4));
        cpasync16(bBase + sw, &wpl[(size_t)(nbc + row) * DINP + off + seg * 8]);
    }
}

__global__ __launch_bounds__(256) void k_gemm1t(const float* __restrict__ b1) {
    extern __shared__ __align__(16) unsigned char dsm[];
    __shared__ float shs[128];

    int tid = threadIdx.x;
    int warp = tid >> 5, lane = tid & 31;
    int nbc = blockIdx.x * 128, mbc = blockIdx.y * 64;
    int wm = (warp >> 2) * 32, wn = (warp & 3) * 32;
    if (tid < 128) shs[tid] = 0.f;

    u32 smem0 = (u32)__cvta_generic_to_shared(dsm);
    u32 aB[3] = {smem0, smem0 + ABUF, smem0 + 2 * ABUF};
    u32 bB[3] = {smem0 + 3 * ABUF, smem0 + 3 * ABUF + BBUF, smem0 + 3 * ABUF + 2 * BBUF};

    float acc[2][4][4];
#pragma unroll
    for (int i = 0; i < 2; i++)
#pragma unroll
        for (int j = 0; j < 4; j++)
#pragma unroll
            for (int q = 0; q < 4; q++) acc[i][j][q] = 0.f;

    // per-lane ldmatrix row indices (swizzle applied per-ks)
    int arow0 = wm + (lane & 15);            // + h*16
    int akg   = lane >> 4;                    // 0/1 -> which 16B within k16
    int brow0 = wn + (lane & 7) + ((lane >> 4) & 1) * 8;  // + g*16
    int bkg   = (lane >> 3) & 1;

    // prologue: stage 0,1
    load_chunk(0, aB[0], bB[0], mbc, nbc, tid); cp_commit();
    load_chunk(1, aB[1], bB[1], mbc, nbc, tid); cp_commit();

    int buf = 0;
    for (int c = 0; c < NCHUNK; c++) {
        cp_wait1();
        __syncthreads();
        // issue stage c+2 (after barrier: buffer (c+2)%3 fully consumed at iter c-1)
        if (c + 2 < NCHUNK) {
            int nb2 = (c + 2) % 3;
            load_chunk(c + 2, aB[nb2], bB[nb2], mbc, nbc, tid);
        }
        cp_commit();

        u32 aBase = aB[buf], bBase = bB[buf];
#pragma unroll
        for (int ks = 0; ks < 4; ks++) {
            u32 a0, a1, a2, a3, a4, a5, a6, a7;
            u32 p0, p1, p2, p3, q0, q1, q2, q3;
            int segA = 2 * ks + akg;
            int rA0 = arow0, rA1 = arow0 + 16;
            ldm4(aBase + (u32)(rA0 * 128 + ((segA ^ (rA0 & 7)) << 4)), a0, a1, a2, a3);
            ldm4(aBase + (u32)(rA1 * 128 + ((segA ^ (rA1 & 7)) << 4)), a4, a5, a6, a7);
            int segB = 2 * ks + bkg;
            int rB0 = brow0, rB1 = brow0 + 16;
            ldm4(bBase + (u32)(rB0 * 128 + ((segB ^ (rB0 & 7)) << 4)), p0, p1, p2, p3);
            ldm4(bBase + (u32)(rB1 * 128 + ((segB ^ (rB1 & 7)) << 4)), q0, q1, q2, q3);

            mma16816(acc[0][0][0], acc[0][0][1], acc[0][0][2], acc[0][0][3], a0, a1, a2, a3, p0, p1);
            mma16816(acc[0][1][0], acc[0][1][1], acc[0][1][2], acc[0][1][3], a0, a1, a2, a3, p2, p3);
            mma16816(acc[0][2][0], acc[0][2][1], acc[0][2][2], acc[0][2][3], a0, a1, a2, a3, q0, q1);
            mma16816(acc[0][3][0], acc[0][3][1], acc[0][3][2], acc[0][3][3], a0, a1, a2, a3, q2, q3);
            mma16816(acc[1][0][0], acc[1][0][1], acc[1][0][2], acc[1][0][3], a4, a5, a6, a7, p0, p1);
            mma16816(acc[1][1][0], acc[1][1][1], acc[1][1][2], acc[1][1][3], a4, a5, a6, a7, p2, p3);
            mma16816(acc[1][2][0], acc[1][2][1], acc[1][2][2], acc[1][2][3], a4, a5, a6, a7, q0, q1);
            mma16816(acc[1][3][0], acc[1][3][1], acc[1][3][2], acc[1][3][3], a4, a5, a6, a7, q2, q3);
        }
        buf = (buf + 1) % 3;
    }

    // ---------------- fused LIF epilogue (verified fragment mapping) ----------------
    int r0 = lane >> 2, cp = (lane & 3) * 2;
    float csum[4][2];
#pragma unroll
    for (int j = 0; j < 4; j++) { csum[j][0] = 0.f; csum[j][1] = 0.f; }

#pragma unroll
    for (int j = 0; j < 4; j++) {
        int col = nbc + wn + j * 8 + cp;
        float2 bias = *(const float2*)&b1[col];
#pragma unroll
        for (int i = 0; i < 2; i++) {
#pragma unroll
            for (int h = 0; h < 2; h++) {
                int row = mbc + wm + i * 16 + r0 + h * 8;
                size_t idx = (size_t)row * NH1 + col;
                float2 om = *(float2*)&g_h1m[idx];
                float2 os = *(float2*)&g_h1s[idx];
                float v0 = acc[i][j][2 * h + 0] + bias.x + om.x * 0.2f * (1.f - os.x);
                float v1 = acc[i][j][2 * h + 1] + bias.y + om.y * 0.2f * (1.f - os.y);
                float s0 = v0 > 0.5f ? 1.f : 0.f;
                float s1 = v1 > 0.5f ? 1.f : 0.f;
                float2 vm = {v0, v1}, vs = {s0, s1};
                *(float2*)&g_h1m[idx] = vm;
                *(float2*)&g_h1s[idx] = vs;
                csum[j][0] += s0; csum[j][1] += s1;
            }
        }
    }
#pragma unroll
    for (int j = 0; j < 4; j++) {
        atomicAdd(&shs[wn + j * 8 + cp],     csum[j][0]);
        atomicAdd(&shs[wn + j * 8 + cp + 1], csum[j][1]);
    }
    __syncthreads();
    if (tid < 128) atomicAdd(&g_hs[nbc + tid], shs[tid]);
}

// ---------------- fused layer-2 LIF + scalar dots (one launch) ----------------
__global__ __launch_bounds__(256) void k_h2dot(const float* __restrict__ W2,
                                               const float* __restrict__ b2) {
    int tid = threadIdx.x;
    if (blockIdx.x < NB / 4) {
        int b0 = blockIdx.x * 4;
        float acc[4][10];
#pragma unroll
        for (int r = 0; r < 4; r++)
#pragma unroll
            for (int k = 0; k < 10; k++) acc[r][k] = 0.f;

        for (int j = tid; j < NH1; j += 256) {
            float w[10];
#pragma unroll
            for (int k = 0; k < 10; k++) w[k] = W2[k * NH1 + j];
#pragma unroll
            for (int r = 0; r < 4; r++) {
                float s = g_h1s[(size_t)(b0 + r) * NH1 + j];
#pragma unroll
                for (int k = 0; k < 10; k++) acc[r][k] += s * w[k];
            }
        }
#pragma unroll
        for (int r = 0; r < 4; r++)
#pragma unroll
            for (int k = 0; k < 10; k++)
#pragma unroll
                for (int o = 16; o; o >>= 1)
                    acc[r][k] += __shfl_down_sync(0xffffffffu, acc[r][k], o);

        __shared__ float sh[8][40];
        int lane = tid & 31, wrp = tid >> 5;
        if (lane == 0) {
#pragma unroll
            for (int r = 0; r < 4; r++)
#pragma unroll
                for (int k = 0; k < 10; k++) sh[wrp][r * 10 + k] = acc[r][k];
        }
        __syncthreads();
        if (tid < 40) {
            float v = 0.f;
#pragma unroll
            for (int w8 = 0; w8 < 8; w8++) v += sh[w8][tid];
            int r = tid / 10, k = tid % 10;
            int idx = (b0 + r) * NH2 + k;
            float m = g_h2m[idx] * 0.2f * (1.f - g_h2s[idx]) + v + b2[k];
            float s = m > 0.5f ? 1.f : 0.f;
            g_h2m[idx] = m; g_h2s[idx] = s; g_h2sum[idx] += s;
        }
    } else {
        // scalar dots + zero xs/hs for next step
        float t1 = 0.f, t2 = 0.f, tc = 0.f;
        for (int u = tid; u < NU; u += 256) {
            float w = (u < DIN) ? g_xs[u] : g_hs[u - DIN];
            t1 += w * g_v1[u];
            t2 += w * g_v2[u];
            tc += w;
        }
        __shared__ float s1[256], s2[256], sc[256];
        s1[tid] = t1; s2[tid] = t2; sc[tid] = tc;
        __syncthreads();
        for (int o = 128; o; o >>= 1) {
            if (tid < o) { s1[tid] += s1[tid + o]; s2[tid] += s2[tid + o]; sc[tid] += sc[tid + o]; }
            __syncthreads();
        }
        if (tid == 0) { g_scal[0] += s1[0]; g_scal[1] += s2[0]; g_scal[2] += sc[0]; }
        __syncthreads();
        for (int u = tid; u < DIN; u += 256) g_xs[u] = 0.f;
        for (int u = tid; u < NH1; u += 256) g_hs[u] = 0.f;
    }
}

// ---------------- output: (h2sum/T, a1, a2, cs) ----------------
__global__ void k_out(float* __restrict__ out) {
    int i = blockIdx.x * blockDim.x + threadIdx.x;
    if (i < NB * NH2) out[i] = g_h2sum[i] / (float)TSTEPS;
    else if (i < NB * NH2 + 3) out[i] = g_scal[i - NB * NH2];
}

extern "C" void kernel_launch(void* const* d_in, const int* in_sizes, int n_in,
                              void* d_out, int out_size) {
    const float* inp = (const float*)d_in[0];
    const float* W1  = (const float*)d_in[1];
    const float* b1  = (const float*)d_in[2];
    const float* W2  = (const float*)d_in[3];
    const float* b2  = (const float*)d_in[4];
    const float* cmv = (const float*)d_in[5];
    const int*   cmc = (const int*)d_in[6];

    cudaFuncSetAttribute(k_gemm1t, cudaFuncAttributeMaxDynamicSharedMemorySize, DSMEM_SZ);

    k_init<<<2048, 256>>>();
    k_split<<<(NH1 * DINP + 255) / 256, 256>>>(W1);
    k_val<<<(NU + 255) / 256, 256>>>(cmv, cmc);

    for (int t = 0; t < TSTEPS; t++) {
        dim3 gr((DIN + 255) / 256, NB / 16);
        k_rng<<<gr, 256>>>(inp, t);
        dim3 g1(NH1 / 128, NB / 64);
        k_gemm1t<<<g1, 256, DSMEM_SZ>>>(b1);
        k_h2dot<<<NB / 4 + 1, 256>>>(W2, b2);
    }
    k_out<<<(NB * NH2 + 3 + 255) / 256, 256>>>((float*)d_out);
}